// round 1
// baseline (speedup 1.0000x reference)
#include <cuda_runtime.h>
#include <cstdint>

// Problem constants
#define B      16
#define T      4096
#define D      256
#define TOPK   7
#define NBLK1  (B * D / 8)        // 512 blocks, each handles 8 channels of one batch
#define NTHR1  512

// Params per series: float4(k_as_int_bits, C=Re/1024, S=Im/1024, 0)
__device__ float4 g_params[B * D * TOPK];

__device__ __forceinline__ float2 cmul(float2 a, float2 b) {
    return make_float2(a.x * b.x - a.y * b.y, a.x * b.y + a.y * b.x);
}

__device__ __forceinline__ int digit_rev_4096(int t) {
    // reverse 6 base-4 digits of a 12-bit index
    unsigned r = __brev((unsigned)t) >> 20;           // bit-reverse 12 bits
    r = ((r & 0x555u) << 1) | ((r >> 1) & 0x555u);    // swap bits within each pair
    return (int)r;
}

// ---------------------------------------------------------------------------
// Kernel 1: per-(b, 8-channel-group) FFT + top-7 selection
// smem: z[4*4096] float2 | tw[4096] float2 | cand[512*7] float2
// ---------------------------------------------------------------------------
__global__ __launch_bounds__(NTHR1)
void fft_topk_kernel(const float* __restrict__ x) {
    extern __shared__ float2 smem[];
    float2* z    = smem;               // 4 packed complex series, 4096 each
    float2* tw   = z + 4 * T;          // twiddle table exp(-2*pi*i*k/4096)
    float2* cand = tw + T;             // 512 threads * 7 candidates

    const int tid = threadIdx.x;
    const int blk = blockIdx.x;
    const int b   = blk >> 5;          // /32
    const int d0  = (blk & 31) * 8;

    // Twiddle table: tw[k] = exp(-2*pi*i*k/4096) = (cos(pi*k/2048), -sin(pi*k/2048))
    for (int i = tid; i < T; i += NTHR1) {
        float s, c;
        sincospif((float)i * (1.0f / 2048.0f), &s, &c);
        tw[i] = make_float2(c, -s);
    }

    // Load 8 channels, pack pairs into 4 complex series, store digit-reversed
    for (int t = tid; t < T; t += NTHR1) {
        const float* row = x + (((size_t)b * T + t) * D + d0);
        float4 v0 = *reinterpret_cast<const float4*>(row);
        float4 v1 = *reinterpret_cast<const float4*>(row + 4);
        int r = digit_rev_4096(t);
        z[0 * T + r] = make_float2(v0.x, v0.y);
        z[1 * T + r] = make_float2(v0.z, v0.w);
        z[2 * T + r] = make_float2(v1.x, v1.y);
        z[3 * T + r] = make_float2(v1.z, v1.w);
    }

    // 6 radix-4 DIT stages
    for (int s = 0; s < 6; s++) {
        const int q   = 1 << (2 * s);        // quarter size
        const int m   = q << 2;              // sub-FFT size
        const int tws = T >> (2 * (s + 1));  // 4096 / m
        __syncthreads();
        #pragma unroll 2
        for (int bf = tid; bf < 4096; bf += NTHR1) {
            const int series = bf >> 10;
            const int u      = bf & 1023;
            const int g      = u >> (2 * s);
            const int j      = u & (q - 1);
            const int base   = series * T + g * m + j;

            float2 a0 = z[base];
            float2 x1 = z[base + q];
            float2 x2 = z[base + 2 * q];
            float2 x3 = z[base + 3 * q];

            const int ji = j * tws;
            float2 a1 = cmul(x1, tw[ji]);
            float2 a2 = cmul(x2, tw[2 * ji]);
            float2 a3 = cmul(x3, tw[3 * ji]);

            float2 t0 = make_float2(a0.x + a2.x, a0.y + a2.y);
            float2 t1 = make_float2(a0.x - a2.x, a0.y - a2.y);
            float2 t2 = make_float2(a1.x + a3.x, a1.y + a3.y);
            float2 t3 = make_float2(a1.x - a3.x, a1.y - a3.y);

            z[base]         = make_float2(t0.x + t2.x, t0.y + t2.y);
            z[base + q]     = make_float2(t1.x + t3.y, t1.y - t3.x);  // t1 - i*t3
            z[base + 2 * q] = make_float2(t0.x - t2.x, t0.y - t2.y);
            z[base + 3 * q] = make_float2(t1.x - t3.y, t1.y + t3.x);  // t1 + i*t3
        }
    }
    __syncthreads();

    // --- magnitude scan + per-thread top-7 ---
    // 64 threads per real series; series sid = tid>>6 (0..7)
    const int sid = tid >> 6;
    const int l64 = tid & 63;
    const int c   = sid >> 1;
    const int isB = sid & 1;

    float m2[TOPK];
    int   kk[TOPK];
    #pragma unroll
    for (int p = 0; p < TOPK; p++) { m2[p] = -1.0f; kk[p] = 1; }

    for (int k = 1 + l64; k < 2048; k += 64) {
        float2 Zk = z[c * T + k];
        float2 Zn = z[c * T + (T - k)];
        float re, im;
        if (!isB) { re = 0.5f * (Zk.x + Zn.x); im = 0.5f * (Zk.y - Zn.y); }
        else      { re = 0.5f * (Zk.y + Zn.y); im = 0.5f * (Zn.x - Zk.x); }
        float mg = re * re + im * im;
        int kkk = k;
        #pragma unroll
        for (int p = 0; p < TOPK; p++) {
            if (mg > m2[p]) {
                float tm = m2[p]; m2[p] = mg; mg = tm;
                int   tk = kk[p]; kk[p] = kkk; kkk = tk;
            }
        }
    }
    #pragma unroll
    for (int p = 0; p < TOPK; p++)
        cand[tid * TOPK + p] = make_float2(m2[p], __int_as_float(kk[p]));
    __syncthreads();

    // --- merge: one lane per series scans its 64*7 candidates ---
    if (tid < 8) {
        const int ms  = tid;
        const int mc  = ms >> 1;
        const int mb  = ms & 1;
        float M2[TOPK];
        int   K[TOPK];
        #pragma unroll
        for (int p = 0; p < TOPK; p++) { M2[p] = -2.0f; K[p] = 1; }

        for (int u = 0; u < 64; u++) {
            const float2* src = cand + (ms * 64 + u) * TOPK;
            for (int p = 0; p < TOPK; p++) {
                float2 cd = src[p];
                float mg = cd.x;
                if (mg <= M2[TOPK - 1]) break;   // sorted source -> early out
                int kkk = __float_as_int(cd.y);
                #pragma unroll
                for (int q2 = 0; q2 < TOPK; q2++) {
                    if (mg > M2[q2]) {
                        float tm = M2[q2]; M2[q2] = mg; mg = tm;
                        int   tk = K[q2];  K[q2] = kkk; kkk = tk;
                    }
                }
            }
        }

        const int seriesGlobal = b * D + d0 + 2 * mc + mb;
        #pragma unroll
        for (int p = 0; p < TOPK; p++) {
            int k = K[p];
            float2 Zk = z[mc * T + k];
            float2 Zn = z[mc * T + (T - k)];
            float re, im;
            if (!mb) { re = 0.5f * (Zk.x + Zn.x); im = 0.5f * (Zk.y - Zn.y); }
            else     { re = 0.5f * (Zk.y + Zn.y); im = 0.5f * (Zn.x - Zk.x); }
            g_params[seriesGlobal * TOPK + p] =
                make_float4(__int_as_float(k), re * (1.0f / 1024.0f),
                            im * (1.0f / 1024.0f), 0.0f);
        }
    }
}

// ---------------------------------------------------------------------------
// Kernel 2: reconstruction. block = (t-chunk of 256, batch), thread = channel.
// out[b,t,d] = sum_j C_j*cos(2*pi*k_j*t/4096) - S_j*sin(...)
// Phasor rotation recurrence, exact start phase via integer mod.
// ---------------------------------------------------------------------------
__global__ __launch_bounds__(256)
void reconstruct_kernel(float* __restrict__ out) {
    const int d  = threadIdx.x;
    const int b  = blockIdx.y;
    const int t0 = blockIdx.x * 256;
    const int series = b * D + d;

    float C[TOPK], S[TOPK], cs[TOPK], sn[TOPK], cD[TOPK], sD[TOPK];
    #pragma unroll
    for (int j = 0; j < TOPK; j++) {
        float4 p = g_params[series * TOPK + j];
        int k = __float_as_int(p.x);
        C[j] = p.y; S[j] = p.z;
        int m0 = (k * t0) & (T - 1);
        sincospif((float)m0 * (1.0f / 2048.0f), &sn[j], &cs[j]);
        sincospif((float)k  * (1.0f / 2048.0f), &sD[j], &cD[j]);
    }

    float* orow = out + (((size_t)b * T + t0) * D + d);
    for (int tt = 0; tt < 256; tt++) {
        float acc = 0.0f;
        #pragma unroll
        for (int j = 0; j < TOPK; j++) {
            acc = fmaf(C[j], cs[j], acc);
            acc = fmaf(-S[j], sn[j], acc);
        }
        orow[(size_t)tt * D] = acc;
        #pragma unroll
        for (int j = 0; j < TOPK; j++) {
            float nc = cs[j] * cD[j] - sn[j] * sD[j];
            float ns = cs[j] * sD[j] + sn[j] * cD[j];
            cs[j] = nc; sn[j] = ns;
        }
    }
}

// ---------------------------------------------------------------------------
extern "C" void kernel_launch(void* const* d_in, const int* in_sizes, int n_in,
                              void* d_out, int out_size) {
    const float* x = (const float*)d_in[0];
    float* out = (float*)d_out;

    const size_t smem_bytes = (4 * T + T + NTHR1 * TOPK) * sizeof(float2); // 192512
    cudaFuncSetAttribute(fft_topk_kernel,
                         cudaFuncAttributeMaxDynamicSharedMemorySize,
                         (int)smem_bytes);

    fft_topk_kernel<<<NBLK1, NTHR1, smem_bytes>>>(x);
    reconstruct_kernel<<<dim3(T / 256, B), 256>>>(out);
}

// round 2
// speedup vs baseline: 2.9181x; 2.9181x over previous
#include <cuda_runtime.h>
#include <cstdint>

#define B      16
#define T      4096
#define D      256
#define TOPK   7

// padded smem index: +1 float2 every 16 (kills stride-16 conflicts in pass 3)
#define SPAD(i) ((i) + ((i) >> 4))
#define SER_PAD 4352               // SPAD(4095)=4350, round up

// per-series params: float4(k_as_int_bits, C=Re/1024, S=Im/1024, 0)
__device__ float4 g_params[B * D * TOPK];

__device__ __forceinline__ float2 cmul(float2 a, float2 b) {
    return make_float2(a.x * b.x - a.y * b.y, a.x * b.y + a.y * b.x);
}
__device__ __forceinline__ float2 cmulf(float2 a, float br, float bi) {
    return make_float2(a.x * br - a.y * bi, a.x * bi + a.y * br);
}

// forward radix-4 butterfly, W4 = -i, in place
__device__ __forceinline__ void bf4(float2& a0, float2& a1, float2& a2, float2& a3) {
    float2 t0 = make_float2(a0.x + a2.x, a0.y + a2.y);
    float2 t1 = make_float2(a0.x - a2.x, a0.y - a2.y);
    float2 t2 = make_float2(a1.x + a3.x, a1.y + a3.y);
    float2 t3 = make_float2(a1.x - a3.x, a1.y - a3.y);
    a0 = make_float2(t0.x + t2.x, t0.y + t2.y);
    a1 = make_float2(t1.x + t3.y, t1.y - t3.x);   // t1 - i*t3
    a2 = make_float2(t0.x - t2.x, t0.y - t2.y);
    a3 = make_float2(t1.x - t3.y, t1.y + t3.x);   // t1 + i*t3
}

// 16-point forward DFT. Input r[n] natural order.
// Output: Y[alpha] lives in slot ((alpha&3)<<2)|(alpha>>2)  (base-4 digit swap).
__device__ __forceinline__ void dft16(float2* r) {
    const float C1 = 0.9238795325112867f;   // cos(pi/8)
    const float S1 = 0.3826834323650898f;   // sin(pi/8)
    const float A  = 0.7071067811865476f;   // sqrt(2)/2
    // stage 1: radix-4 over n2 (slots {n1, n1+4, n1+8, n1+12}), then W16^{n1*k2}
    bf4(r[0], r[4], r[8],  r[12]);                       // n1=0, no twiddle
    bf4(r[1], r[5], r[9],  r[13]);                       // n1=1
    r[5]  = cmulf(r[5],  C1, -S1);
    r[9]  = cmulf(r[9],  A,  -A);
    r[13] = cmulf(r[13], S1, -C1);
    bf4(r[2], r[6], r[10], r[14]);                       // n1=2
    r[6]  = cmulf(r[6],  A,  -A);
    r[10] = make_float2(r[10].y, -r[10].x);              // * (0,-1)
    r[14] = cmulf(r[14], -A, -A);
    bf4(r[3], r[7], r[11], r[15]);                       // n1=3
    r[7]  = cmulf(r[7],  S1, -C1);
    r[11] = cmulf(r[11], -A, -A);
    r[15] = cmulf(r[15], -C1, S1);
    // stage 2: radix-4 over n1 (slots {4k2..4k2+3}); Y[k2+4k1] -> slot 4k2+k1
    bf4(r[0],  r[1],  r[2],  r[3]);
    bf4(r[4],  r[5],  r[6],  r[7]);
    bf4(r[8],  r[9],  r[10], r[11]);
    bf4(r[12], r[13], r[14], r[15]);
}

// ---------------------------------------------------------------------------
// Kernel 1: block = (batch, 4 channels) -> 2 packed complex 4096-pt FFTs
// 512 threads: tid>>8 = series, tid&255 = lane within series.
// 3 register-resident radix-16 passes + 7-round parallel argmax top-k.
// ---------------------------------------------------------------------------
__global__ __launch_bounds__(512, 2)
void fft_topk_kernel(const float* __restrict__ x) {
    extern __shared__ float2 sm[];
    float2* zz   = sm;                       // 2 * SER_PAD
    float2* red  = sm + 2 * SER_PAD;         // [series*2+ch][8 warps]
    int*    wink = (int*)(red + 32);         // [4]

    const int tid = threadIdx.x;
    const int b   = blockIdx.x >> 6;
    const int d0  = (blockIdx.x & 63) * 4;

    // coalesced load: float4 = 4 channels; pack into 2 complex series
    for (int t = tid; t < T; t += 512) {
        float4 v = *reinterpret_cast<const float4*>(
            x + ((size_t)(b * T + t)) * D + d0);
        zz[SPAD(t)]           = make_float2(v.x, v.y);
        zz[SER_PAD + SPAD(t)] = make_float2(v.z, v.w);
    }
    __syncthreads();

    const int sid = tid >> 8;
    const int tl  = tid & 255;
    float2* Z = zz + sid * SER_PAD;
    float2 r[16];

    // ---------------- pass 1: DFT over a (stride 256) ----------------
    #pragma unroll
    for (int a = 0; a < 16; a++) r[a] = Z[SPAD(a * 256 + tl)];
    dft16(r);
    {   // twiddle W_256^{b2*alpha}, b2 = tl>>4
        const int b2 = tl >> 4;
        float s, c; sincospif((float)b2 * (1.0f / 128.0f), &s, &c);
        float2 w1 = make_float2(c, -s);
        float2 w  = w1;
        #pragma unroll
        for (int al = 1; al < 16; al++) {
            const int sl = ((al & 3) << 2) | (al >> 2);
            r[sl] = cmul(r[sl], w);
            w = cmul(w, w1);
        }
    }
    #pragma unroll
    for (int al = 0; al < 16; al++)
        Z[SPAD(al * 256 + tl)] = r[((al & 3) << 2) | (al >> 2)];
    __syncthreads();

    // ---------------- pass 2: DFT over b (stride 16) ----------------
    {
        const int alpha = tl >> 4, c = tl & 15;
        #pragma unroll
        for (int bb = 0; bb < 16; bb++)
            r[bb] = Z[SPAD(alpha * 256 + bb * 16 + c)];
        dft16(r);
        // twiddle W_4096^{c*(16*beta+alpha)} = W_4096^{c*alpha} * (W_256^c)^beta
        float s0, c0, s1, c1;
        sincospif((float)(c * alpha) * (1.0f / 2048.0f), &s0, &c0);
        sincospif((float)c * (1.0f / 128.0f), &s1, &c1);
        float2 w    = make_float2(c0, -s0);   // base
        float2 step = make_float2(c1, -s1);
        #pragma unroll
        for (int be = 0; be < 16; be++) {
            const int sl = ((be & 3) << 2) | (be >> 2);
            r[sl] = cmul(r[sl], w);
            w = cmul(w, step);
        }
        #pragma unroll
        for (int be = 0; be < 16; be++)
            Z[SPAD(alpha * 256 + be * 16 + c)] = r[((be & 3) << 2) | (be >> 2)];
    }
    __syncthreads();

    // ---------------- pass 3: DFT over c (stride 1), scatter out ----------------
    {
        const int alpha = tl >> 4, beta = tl & 15;
        #pragma unroll
        for (int cc = 0; cc < 16; cc++)
            r[cc] = Z[SPAD(alpha * 256 + beta * 16 + cc)];
        __syncthreads();          // all reads done before cross-thread writes
        dft16(r);
        #pragma unroll
        for (int ga = 0; ga < 16; ga++)
            Z[SPAD(ga * 256 + beta * 16 + alpha)] = r[((ga & 3) << 2) | (ga >> 2)];
    }
    __syncthreads();

    // ---------------- top-7 per real channel (A = even, B = odd) ----------------
    float magA[8], magB[8];
    #pragma unroll
    for (int m = 0; m < 8; m++) {
        int k = m * 256 + tl;
        const bool valid = (k != 0);
        int kk = valid ? k : 1;
        float2 Zk = Z[SPAD(kk)];
        float2 Zn = Z[SPAD(4096 - kk)];
        float reA = 0.5f * (Zk.x + Zn.x), imA = 0.5f * (Zk.y - Zn.y);
        float reB = 0.5f * (Zk.y + Zn.y), imB = 0.5f * (Zn.x - Zk.x);
        magA[m] = valid ? (reA * reA + imA * imA) : -1.0f;
        magB[m] = valid ? (reB * reB + imB * imB) : -1.0f;
    }

    const int wrp = tl >> 5;
    for (int round = 0; round < TOPK; round++) {
        // --- channel A local + warp argmax ---
        float bm = magA[0]; int bk = tl;
        #pragma unroll
        for (int m = 1; m < 8; m++)
            if (magA[m] > bm) { bm = magA[m]; bk = m * 256 + tl; }
        #pragma unroll
        for (int o = 16; o > 0; o >>= 1) {
            float om = __shfl_down_sync(0xFFFFFFFFu, bm, o);
            int   ok = __shfl_down_sync(0xFFFFFFFFu, bk, o);
            if (om > bm) { bm = om; bk = ok; }
        }
        if ((tl & 31) == 0)
            red[(sid * 2 + 0) * 8 + wrp] = make_float2(bm, __int_as_float(bk));
        // --- channel B ---
        bm = magB[0]; bk = tl;
        #pragma unroll
        for (int m = 1; m < 8; m++)
            if (magB[m] > bm) { bm = magB[m]; bk = m * 256 + tl; }
        #pragma unroll
        for (int o = 16; o > 0; o >>= 1) {
            float om = __shfl_down_sync(0xFFFFFFFFu, bm, o);
            int   ok = __shfl_down_sync(0xFFFFFFFFu, bk, o);
            if (om > bm) { bm = om; bk = ok; }
        }
        if ((tl & 31) == 0)
            red[(sid * 2 + 1) * 8 + wrp] = make_float2(bm, __int_as_float(bk));
        __syncthreads();

        if (tid < 4) {                 // tid = series*2 + ch
            const int s2 = tid >> 1, ch = tid & 1;
            float wm = -2.0f; int wk = 1;
            #pragma unroll
            for (int u = 0; u < 8; u++) {
                float2 e = red[tid * 8 + u];
                if (e.x > wm) { wm = e.x; wk = __float_as_int(e.y); }
            }
            float2* Zs = zz + s2 * SER_PAD;
            float2 Zk = Zs[SPAD(wk)];
            float2 Zn = Zs[SPAD(4096 - wk)];
            float re, im;
            if (!ch) { re = 0.5f * (Zk.x + Zn.x); im = 0.5f * (Zk.y - Zn.y); }
            else     { re = 0.5f * (Zk.y + Zn.y); im = 0.5f * (Zn.x - Zk.x); }
            g_params[(size_t)(b * D + d0 + 2 * s2 + ch) * TOPK + round] =
                make_float4(__int_as_float(wk), re * (1.0f / 1024.0f),
                            im * (1.0f / 1024.0f), 0.0f);
            wink[tid] = wk;
        }
        __syncthreads();

        const int wkA = wink[sid * 2 + 0];
        const int wkB = wink[sid * 2 + 1];
        #pragma unroll
        for (int m = 0; m < 8; m++) {
            if (wkA == m * 256 + tl) magA[m] = -1.0f;
            if (wkB == m * 256 + tl) magB[m] = -1.0f;
        }
        __syncthreads();
    }
}

// ---------------------------------------------------------------------------
// Kernel 2: reconstruction via Chebyshev 2-term recurrence.
// g(t) = C*cos(2*pi*k*t/T) - S*sin(...);  g_{t+1} = 2cos(2*pi*k/T)*g_t - g_{t-1}
// block = (128-sample t-chunk, batch), thread = channel. 512 blocks.
// ---------------------------------------------------------------------------
__global__ __launch_bounds__(256)
void reconstruct_kernel(float* __restrict__ out) {
    const int d  = threadIdx.x;
    const int b  = blockIdx.y;
    const int t0 = blockIdx.x * 128;
    const size_t series = (size_t)b * D + d;

    float twoC[TOPK], g[TOPK], gp[TOPK];
    #pragma unroll
    for (int j = 0; j < TOPK; j++) {
        float4 p = g_params[series * TOPK + j];
        int k = __float_as_int(p.x);
        float C = p.y, S = p.z;
        int m0 = (k * (t0 - 1)) & (T - 1);      // exact mod (neg ok: two's complement)
        int m1 = (k * t0) & (T - 1);
        float s, c;
        sincospif((float)m0 * (1.0f / 2048.0f), &s, &c);
        gp[j] = C * c - S * s;                  // g(t0-1)
        sincospif((float)m1 * (1.0f / 2048.0f), &s, &c);
        g[j] = C * c - S * s;                   // g(t0)
        twoC[j] = 2.0f * cospif((float)k * (1.0f / 2048.0f));
    }

    float* orow = out + ((size_t)(b * T + t0)) * D + d;
    for (int tt = 0; tt < 128; tt += 2) {
        float a0 = 0.0f;
        #pragma unroll
        for (int j = 0; j < TOPK; j++) a0 += g[j];
        orow[(size_t)tt * D] = a0;
        #pragma unroll
        for (int j = 0; j < TOPK; j++)
            gp[j] = fmaf(twoC[j], g[j], -gp[j]);    // g(t+1)
        float a1 = 0.0f;
        #pragma unroll
        for (int j = 0; j < TOPK; j++) a1 += gp[j];
        orow[(size_t)(tt + 1) * D] = a1;
        #pragma unroll
        for (int j = 0; j < TOPK; j++)
            g[j] = fmaf(twoC[j], gp[j], -g[j]);     // g(t+2)
    }
}

// ---------------------------------------------------------------------------
extern "C" void kernel_launch(void* const* d_in, const int* in_sizes, int n_in,
                              void* d_out, int out_size) {
    const float* x = (const float*)d_in[0];
    float* out = (float*)d_out;

    const size_t smem_bytes = (2 * SER_PAD + 32) * sizeof(float2) + 4 * sizeof(int);
    cudaFuncSetAttribute(fft_topk_kernel,
                         cudaFuncAttributeMaxDynamicSharedMemorySize,
                         (int)smem_bytes);

    fft_topk_kernel<<<B * D / 4, 512, smem_bytes>>>(x);
    reconstruct_kernel<<<dim3(T / 128, B), 256>>>(out);
}